// round 6
// baseline (speedup 1.0000x reference)
#include <cuda_runtime.h>
#include <cuda_bf16.h>
#include <math.h>
#include <float.h>
#include <stdint.h>

// Problem constants
#define GN   32768
#define GLD  256
#define GD   512
#define KS   1024
#define KM   4096
#define NUNITS 1280   // 256 syn units + 1024 sem units (each: 128 rows x 1024 codes)

// ---------------- scratch (static __device__, no allocation) ----------------
static __device__ float g_esum_syn[KS * GD];
static __device__ float g_esum_sem[KM * GD];
static __device__ float g_counts_syn[KS];
static __device__ float g_counts_sem[KM];
static __device__ int   g_pair_syn[(size_t)KS * KS];
static __device__ int   g_pair_sem[(size_t)KM * KM];
static __device__ int   g_idx_syn[GN];
static __device__ int   g_idx_sem[GN];
static __device__ float g_cnorm_syn[KS];
static __device__ float g_cnorm_sem[KM];
static __device__ float g_clnew_syn[KS];
static __device__ float g_clnew_sem[KM];
static __device__ float g_nsum[2];
static __device__ float g_losspart[512];
static __device__ int   g_maxcn[2];   // float-as-int max of squared code norms
// bf16 copies (16B-aligned for uint4 access)
static __device__ __align__(16) __nv_bfloat16 g_zbf_syn[(size_t)GN * GD];
static __device__ __align__(16) __nv_bfloat16 g_zbf_sem[(size_t)GN * GD];
static __device__ __align__(16) __nv_bfloat16 g_cbf_syn[(size_t)KS * GD];
static __device__ __align__(16) __nv_bfloat16 g_cbf_sem[(size_t)KM * GD];
// candidates: per (unit, local row): 32 slots
static __device__ float g_cv[(size_t)NUNITS * 128 * 32];
static __device__ int   g_ck[(size_t)NUNITS * 128 * 32];

// ---------------- PTX helpers (arch-agnostic) ----------
__device__ __forceinline__ uint32_t smem_u32(const void* p) {
    uint32_t a;
    asm("{ .reg .u64 t; cvta.to.shared.u64 t, %1; cvt.u32.u64 %0, t; }" : "=r"(a) : "l"(p));
    return a;
}
__device__ __forceinline__ void ldsm4(uint32_t& r0, uint32_t& r1, uint32_t& r2, uint32_t& r3,
                                      uint32_t addr) {
    asm volatile("ldmatrix.sync.aligned.m8n8.x4.shared.b16 {%0,%1,%2,%3}, [%4];"
                 : "=r"(r0), "=r"(r1), "=r"(r2), "=r"(r3) : "r"(addr));
}
__device__ __forceinline__ void mma_bf16(float* d, const uint32_t* a, uint32_t b0, uint32_t b1) {
    asm volatile("mma.sync.aligned.m16n8k16.row.col.f32.bf16.bf16.f32 "
                 "{%0,%1,%2,%3}, {%4,%5,%6,%7}, {%8,%9}, {%0,%1,%2,%3};"
                 : "+f"(d[0]), "+f"(d[1]), "+f"(d[2]), "+f"(d[3])
                 : "r"(a[0]), "r"(a[1]), "r"(a[2]), "r"(a[3]), "r"(b0), "r"(b1));
}
#define CP_ASYNC16(dst, src) \
    asm volatile("cp.async.cg.shared.global [%0], [%1], 16;" :: "r"(dst), "l"(src))
#define CP_COMMIT() asm volatile("cp.async.commit_group;" ::: "memory")
#define CP_WAIT2()  asm volatile("cp.async.wait_group 2;" ::: "memory")

// ---------------- generic helpers ----------------
__device__ __forceinline__ float blk_reduce_256(float v) {
    __shared__ float sh[8];
    int lane = threadIdx.x & 31, w = threadIdx.x >> 5;
#pragma unroll
    for (int o = 16; o; o >>= 1) v += __shfl_down_sync(0xffffffffu, v, o);
    if (lane == 0) sh[w] = v;
    __syncthreads();
    if (w == 0) {
        v = (lane < 8) ? sh[lane] : 0.f;
#pragma unroll
        for (int o = 4; o; o >>= 1) v += __shfl_down_sync(0xffffffffu, v, o);
    }
    return v;
}

// ---------------- conversions ----------------
__global__ void cvt_z_kernel(const float* __restrict__ re, const float* __restrict__ im,
                             __nv_bfloat16* __restrict__ out) {
    size_t e = ((size_t)blockIdx.x * 256 + threadIdx.x) * 4;
    int n = (int)(e >> 9), d = (int)(e & 511);
    const float* s = (d < GLD) ? re + (size_t)n * GLD + d : im + (size_t)n * GLD + (d - GLD);
    float4 v = *(const float4*)s;
    __nv_bfloat162 a = __floats2bfloat162_rn(v.x, v.y);
    __nv_bfloat162 b = __floats2bfloat162_rn(v.z, v.w);
    ((__nv_bfloat162*)(out + e))[0] = a;
    ((__nv_bfloat162*)(out + e))[1] = b;
}

// fused codebook convert + per-row squared norms + max
__global__ void cvt_cb_norm_kernel(const float* __restrict__ cb, __nv_bfloat16* __restrict__ out,
                                   float* __restrict__ norms, int* __restrict__ mx) {
    __shared__ float sh[8];
    int t = threadIdx.x, lane = t & 31, w = t >> 5;
    size_t e = ((size_t)blockIdx.x * 256 + t) * 4;
    float4 v = *(const float4*)(cb + e);
    __nv_bfloat162 a = __floats2bfloat162_rn(v.x, v.y);
    __nv_bfloat162 b = __floats2bfloat162_rn(v.z, v.w);
    ((__nv_bfloat162*)(out + e))[0] = a;
    ((__nv_bfloat162*)(out + e))[1] = b;
    float s = v.x * v.x + v.y * v.y + v.z * v.z + v.w * v.w;
#pragma unroll
    for (int o = 16; o; o >>= 1) s += __shfl_xor_sync(0xffffffffu, s, o);
    if (lane == 0) sh[w] = s;
    __syncthreads();
    if (t == 0) {
        float n0 = sh[0] + sh[1] + sh[2] + sh[3];
        norms[blockIdx.x * 2] = n0;
        atomicMax(mx, __float_as_int(n0));
    } else if (t == 128) {
        float n1 = sh[4] + sh[5] + sh[6] + sh[7];
        norms[blockIdx.x * 2 + 1] = n1;
        atomicMax(mx, __float_as_int(n1));
    }
}

// ---------------- HMMA bf16 distance pass (cp.async 4-stage pipeline) ------
// Per unit (CTA, 256 thr = 8 warps in 2m x 4n): 128 rows x 1024 codes, D=512.
// Z resident in SMEM (128 x 512 bf16, row stride 1040B).
// Codebook streamed as 64 chunks (128 codes x 64 d, row stride 144B), 4 stages.
#define SM_Z      0
#define SM_C      133120
#define SM_STAGE  18432
#define SM_TOTAL  (SM_C + 4 * SM_STAGE)   // 206848
#define SM_SV     SM_C
#define SM_SK     (SM_C + 16384)

__global__ __launch_bounds__(256, 1) void dist_hmma_kernel(
    const __nv_bfloat16* __restrict__ zbfA, const __nv_bfloat16* __restrict__ cbfA,
    const float* __restrict__ cnA,
    const __nv_bfloat16* __restrict__ zbfB, const __nv_bfloat16* __restrict__ cbfB,
    const float* __restrict__ cnB,
    float* __restrict__ cvout, int* __restrict__ ckout)
{
    extern __shared__ __align__(16) char smem[];
    char* sZ = smem + SM_Z;
    const uint32_t sbase = smem_u32(smem);

    const int tid = threadIdx.x, wid = tid >> 5, lane = tid & 31;
    const int u = blockIdx.x;

    const __nv_bfloat16 *zsrc, *csrc;
    const float* cn;
    int rowBase, kBase;
    if (u < 256) {
        zsrc = zbfA; csrc = cbfA; cn = cnA; rowBase = u * 128; kBase = 0;
    } else {
        int v = u - 256;
        zsrc = zbfB; csrc = cbfB; cn = cnB;
        rowBase = (v >> 2) * 128; kBase = (v & 3) * 1024;
    }

    // load Z tile: 128 rows x 512 bf16
#pragma unroll
    for (int i = 0; i < 32; i++) {
        int c = tid + 256 * i;       // 16B chunk id, 0..8191
        int r = c >> 6, c8 = c & 63;
        uint4 v = *(const uint4*)(zsrc + (((size_t)(rowBase + r)) << 9) + c8 * 8);
        *(uint4*)(sZ + r * 1040 + c8 * 16) = v;
    }

    const int wm = wid >> 2, wn = wid & 3;
    const uint32_t zaddr0 = sbase + SM_Z +
        (uint32_t)((wm * 64 + (lane & 15)) * 1040 + (lane >> 4) * 16);
    const uint32_t coff = (uint32_t)((wn * 32 + ((lane >> 4) << 3) + (lane & 7)) * 144 +
                                     ((lane >> 3) & 1) * 16);
    const int cid = tid;
    float tv[8][2]; int tk[8][2];
#pragma unroll
    for (int i = 0; i < 8; i++)
#pragma unroll
        for (int s = 0; s < 2; s++) { tv[i][s] = FLT_MAX; tk[i][s] = 0; }

    float acc[4][4][4];
#pragma unroll
    for (int mt = 0; mt < 4; mt++)
#pragma unroll
        for (int nt = 0; nt < 4; nt++)
#pragma unroll
            for (int q = 0; q < 4; q++) acc[mt][nt][q] = 0.f;

    // issue chunk c (tile c>>3, d-chunk c&7) into stage c&3
#define ISSUE(cc) do { \
        int _t = (cc) >> 3, _dc = (cc) & 7; \
        char* _sp = smem + SM_C + ((cc) & 3) * SM_STAGE; \
        _Pragma("unroll") \
        for (int _j = 0; _j < 4; _j++) { \
            int _id = cid + 256 * _j; int _r = _id >> 3, _c8 = _id & 7; \
            uint32_t _d = smem_u32(_sp + _r * 144 + _c8 * 16); \
            const __nv_bfloat16* _g = csrc + (((size_t)(kBase + _t * 128 + _r)) << 9) \
                                      + _dc * 64 + _c8 * 8; \
            CP_ASYNC16(_d, _g); \
        } \
    } while (0)

    ISSUE(0); CP_COMMIT();
    ISSUE(1); CP_COMMIT();
    ISSUE(2); CP_COMMIT();

    for (int c = 0; c < 64; c++) {
        CP_WAIT2();
        __syncthreads();
        if (c + 3 < 64) { ISSUE(c + 3); }
        CP_COMMIT();

        const int dc = c & 7;
        const uint32_t caddr0 = sbase + (uint32_t)(SM_C + (c & 3) * SM_STAGE) + coff;
#pragma unroll
        for (int ks = 0; ks < 4; ks++) {
            uint32_t b[8];
            ldsm4(b[0], b[1], b[2], b[3], caddr0 + ks * 32);
            ldsm4(b[4], b[5], b[6], b[7], caddr0 + 16 * 144 + ks * 32);
            uint32_t a[4][4];
#pragma unroll
            for (int mt = 0; mt < 4; mt++)
                ldsm4(a[mt][0], a[mt][1], a[mt][2], a[mt][3],
                      zaddr0 + (uint32_t)(mt * 16 * 1040 + (dc * 64 + ks * 16) * 2));
#pragma unroll
            for (int mt = 0; mt < 4; mt++)
#pragma unroll
                for (int nt = 0; nt < 4; nt++)
                    mma_bf16(acc[mt][nt], a[mt], b[(nt >> 1) * 4 + (nt & 1) * 2],
                             b[(nt >> 1) * 4 + (nt & 1) * 2 + 1]);
        }

        if (dc == 7) {
            // epilogue: fold tile into per-thread top-2 per row
            const int kTile = kBase + (c >> 3) * 128;
            float cnv[8];
#pragma unroll
            for (int nt = 0; nt < 4; nt++)
#pragma unroll
                for (int cc2 = 0; cc2 < 2; cc2++)
                    cnv[nt * 2 + cc2] = __ldg(&cn[kTile + wn * 32 + nt * 8 + (lane & 3) * 2 + cc2]);
#pragma unroll
            for (int mt = 0; mt < 4; mt++)
#pragma unroll
                for (int half = 0; half < 2; half++) {
                    int i = mt * 2 + half;
#pragma unroll
                    for (int nt = 0; nt < 4; nt++)
#pragma unroll
                        for (int cc2 = 0; cc2 < 2; cc2++) {
                            int col = wn * 32 + nt * 8 + (lane & 3) * 2 + cc2;
                            float s = acc[mt][nt][half * 2 + cc2];
                            float v = fmaf(-2.f, s, cnv[nt * 2 + cc2]);
                            int k = kTile + col;
                            if (v < tv[i][0]) {
                                tv[i][1] = tv[i][0]; tk[i][1] = tk[i][0];
                                tv[i][0] = v; tk[i][0] = k;
                            } else if (v < tv[i][1]) {
                                tv[i][1] = v; tk[i][1] = k;
                            }
                        }
                }
#pragma unroll
            for (int mt = 0; mt < 4; mt++)
#pragma unroll
                for (int nt = 0; nt < 4; nt++)
#pragma unroll
                    for (int q = 0; q < 4; q++) acc[mt][nt][q] = 0.f;
        }
    }

    // stage candidates in SMEM (reuse stage area), then coalesced store
    __syncthreads();
    float* sv = (float*)(smem + SM_SV);
    int*   sk = (int*)(smem + SM_SK);
#pragma unroll
    for (int i = 0; i < 8; i++) {
        int r = wm * 64 + (i >> 1) * 16 + (i & 1) * 8 + (lane >> 2);
        int slot0 = wn * 8 + (lane & 3) * 2;
#pragma unroll
        for (int s = 0; s < 2; s++) {
            sv[r * 32 + slot0 + s] = tv[i][s];
            sk[r * 32 + slot0 + s] = tk[i][s];
        }
    }
    __syncthreads();
#pragma unroll
    for (int j = 0; j < 16; j++) {
        int idx = tid + 256 * j;
        cvout[(size_t)u * 4096 + idx] = sv[idx];
        ckout[(size_t)u * 4096 + idx] = sk[idx];
    }
#undef ISSUE
}

// ---------------- exact fp32 refinement ----------------
__global__ __launch_bounds__(256) void refine_kernel(
    const float* __restrict__ zreA, const float* __restrict__ zimA,
    const float* __restrict__ cbA, const float* __restrict__ cnA,
    const float* __restrict__ zreB, const float* __restrict__ zimB,
    const float* __restrict__ cbB, const float* __restrict__ cnB,
    const float* __restrict__ cv, const int* __restrict__ ck,
    const int* __restrict__ maxcn,
    int* __restrict__ idxA, int* __restrict__ idxB)
{
    int wid = threadIdx.x >> 5, lane = threadIdx.x & 31;
    int gw = blockIdx.x * 8 + wid;
    int n = gw >> 1, cbk = gw & 1;
    const float *zre, *zim, *cb, *cn;
    int* idxo;
    int cnt;
    size_t base;
    if (cbk == 0) {
        zre = zreA; zim = zimA; cb = cbA; cn = cnA; idxo = idxA;
        cnt = 32; base = ((size_t)(n >> 7) * 128 + (n & 127)) * 32;
    } else {
        zre = zreB; zim = zimB; cb = cbB; cn = cnB; idxo = idxB;
        cnt = 128; base = ((size_t)(256 + (n >> 7) * 4) * 128 + (n & 127)) * 32;
    }

    float zr[16];
    float zn2 = 0.f;
#pragma unroll
    for (int j = 0; j < 16; j++) {
        int d = lane + 32 * j;
        float z = (d < GLD) ? zre[(size_t)n * GLD + d] : zim[(size_t)n * GLD + d - GLD];
        zr[j] = z;
        zn2 = fmaf(z, z, zn2);
    }
#pragma unroll
    for (int o = 16; o; o >>= 1) zn2 += __shfl_xor_sync(0xffffffffu, zn2, o);

    float vb = FLT_MAX;
    for (int c = lane; c < cnt; c += 32) {
        float v = cv[base + (size_t)(c >> 5) * 4096 + (c & 31)];
        vb = fminf(vb, v);
    }
#pragma unroll
    for (int o = 16; o; o >>= 1) vb = fminf(vb, __shfl_xor_sync(0xffffffffu, vb, o));

    float maxc2 = __int_as_float(maxcn[cbk]);
    float vlim = vb + 0.03125f * sqrtf(zn2 * maxc2) + 0.125f;

    float bd = FLT_MAX; int bk = 0x7fffffff;
    for (int i = 0; i < cnt; i++) {
        size_t a = base + (size_t)(i >> 5) * 4096 + (i & 31);
        float v = cv[a];
        if (v <= vlim) {
            int k = ck[a];
            const float* crow = cb + (size_t)k * GD;
            float s = 0.f;
#pragma unroll
            for (int j = 0; j < 16; j++) s = fmaf(zr[j], crow[lane + 32 * j], s);
#pragma unroll
            for (int o = 16; o; o >>= 1) s += __shfl_xor_sync(0xffffffffu, s, o);
            float d = fmaf(-2.f, s, cn[k]);
            if (d < bd || (d == bd && k < bk)) { bd = d; bk = k; }
        }
    }
    if (lane == 0) idxo[n] = bk;
}

// ---- fused per-row: counts/pair scatter + esum scatter + zq write + loss ----
__global__ __launch_bounds__(128) void fuse_row_kernel(
    const float* __restrict__ zre, const float* __restrict__ zim,
    const int* __restrict__ idx, const int* __restrict__ prev,
    const float* __restrict__ cb,
    float* __restrict__ counts, float* __restrict__ esum, int* __restrict__ pair, int K,
    float* __restrict__ zq, float* __restrict__ idxf, float* __restrict__ lossPart)
{
    __shared__ float sh[4];
    int n = blockIdx.x, t = threadIdx.x;
    int lane = t & 31, w = t >> 5;
    int i = idx[n];
    if (t == 0) {
        atomicAdd(&counts[i], 1.f);
        atomicAdd(&pair[(size_t)prev[n] * K + i], 1);
        idxf[n] = (float)i;
    }
    int d = t * 4;
    const float* zsrc = (d < GLD) ? zre + (size_t)n * GLD + d
                                  : zim + (size_t)n * GLD + (d - GLD);
    float4 z = *(const float4*)zsrc;
    float4 q = *(const float4*)(cb + (size_t)i * GD + d);
    *(float4*)(zq + (size_t)n * GD + d) = q;
    float dx = q.x - z.x, dy = q.y - z.y, dz = q.z - z.z, dw = q.w - z.w;
    float s = dx * dx + dy * dy + dz * dz + dw * dw;
    float* es = esum + (size_t)i * GD + d;
    atomicAdd(es + 0, z.x);
    atomicAdd(es + 1, z.y);
    atomicAdd(es + 2, z.z);
    atomicAdd(es + 3, z.w);
#pragma unroll
    for (int o = 16; o; o >>= 1) s += __shfl_down_sync(0xffffffffu, s, o);
    if (lane == 0) sh[w] = s;
    __syncthreads();
    if (t == 0) atomicAdd(&lossPart[n & 511], sh[0] + sh[1] + sh[2] + sh[3]);
}

// ---------------- cluster_size EMA + n reduction ----------------
__global__ void clnew_kernel(const float* __restrict__ cl, const float* __restrict__ counts,
                             float* __restrict__ clnew, float* __restrict__ nsum, int K)
{
    int k = blockIdx.x * 256 + threadIdx.x;
    float v = 0.f;
    if (k < K) {
        v = cl[k] * 0.99f + 0.01f * counts[k];
        clnew[k] = v;
    }
    v = blk_reduce_256(v);
    if (threadIdx.x == 0) atomicAdd(nsum, v);
}

// ---------------- codebook EMA update ----------------
__global__ void cbnew_kernel(const float* __restrict__ avg, const float* __restrict__ esum,
                             const float* __restrict__ clnew, const float* __restrict__ nsum,
                             float* __restrict__ out, int K)
{
    size_t idx = (size_t)blockIdx.x * 256 + threadIdx.x;
    int k = (int)(idx >> 9);
    float n = *nsum;
    float cs = (clnew[k] + 1e-6f) / (n + (float)K * 1e-6f) * n;
    float a = avg[idx] * 0.99f + 0.01f * esum[idx];
    out[idx] = a / cs;
}

__global__ void finalize_loss_kernel(const float* __restrict__ lacc, float* __restrict__ out) {
    __shared__ float sh[8];
    int t = threadIdx.x, lane = t & 31, w = t >> 5;
    float s = lacc[t] + lacc[t + 256];
#pragma unroll
    for (int o = 16; o; o >>= 1) s += __shfl_down_sync(0xffffffffu, s, o);
    if (lane == 0) sh[w] = s;
    __syncthreads();
    if (t == 0) {
        float v = 0.f;
#pragma unroll
        for (int j = 0; j < 8; j++) v += sh[j];
        out[0] = 1.25f * v / 16777216.f;
    }
}

// ---------------- adjacency transform (vector loads, scalar stores) --------
// NOTE: out may be only 4B-aligned (odd element offset in d_out) — scalar STG.
__device__ __forceinline__ float adj1(float a, int c) {
    if (c == 0) return a;
    float p = powf(0.99f, (float)c);
    return fmaf(a, p, (1.f - p) * 100.f);
}
__global__ void adj_kernel(const float* __restrict__ adj, const int* __restrict__ cnt,
                           float* __restrict__ out, size_t total)
{
    size_t i = ((size_t)blockIdx.x * 256 + threadIdx.x) * 4;
    if (i >= total) return;
    int4 c = *(const int4*)(cnt + i);
    float4 a = *(const float4*)(adj + i);
    out[i + 0] = adj1(a.x, c.x);
    out[i + 1] = adj1(a.y, c.y);
    out[i + 2] = adj1(a.z, c.z);
    out[i + 3] = adj1(a.w, c.w);
}

// ---------------- launch ----------------
extern "C" void kernel_launch(void* const* d_in, const int* in_sizes, int n_in,
                              void* d_out, int out_size)
{
    const float* zre_f = (const float*)d_in[0];
    const float* zim_f = (const float*)d_in[1];
    const float* zre_s = (const float*)d_in[2];
    const float* zim_s = (const float*)d_in[3];
    const int*   prev_syn = (const int*)d_in[4];
    const int*   prev_sem = (const int*)d_in[5];
    const float* cb_syn = (const float*)d_in[6];
    const float* cb_sem = (const float*)d_in[7];
    const float* cl_syn = (const float*)d_in[8];
    const float* avg_syn = (const float*)d_in[9];
    const float* cl_sem = (const float*)d_in[10];
    const float* avg_sem = (const float*)d_in[11];
    const float* adj_syn = (const float*)d_in[12];
    const float* adj_sem = (const float*)d_in[13];

    float* out = (float*)d_out;
    const size_t OFF_ZQ_SYN = 0;
    const size_t OFF_ZQ_SEM = OFF_ZQ_SYN + (size_t)GN * GD;
    const size_t OFF_LOSS   = OFF_ZQ_SEM + (size_t)GN * GD;
    const size_t OFF_IDX_SYN = OFF_LOSS + 1;
    const size_t OFF_IDX_SEM = OFF_IDX_SYN + GN;
    const size_t OFF_CB_SYN  = OFF_IDX_SEM + GN;
    const size_t OFF_CB_SEM  = OFF_CB_SYN + (size_t)KS * GD;
    const size_t OFF_ADJ_SYN = OFF_CB_SEM + (size_t)KM * GD;
    const size_t OFF_ADJ_SEM = OFF_ADJ_SYN + (size_t)KS * KS;

    void *p_esum_syn, *p_esum_sem, *p_cnt_syn, *p_cnt_sem, *p_pair_syn, *p_pair_sem;
    void *p_idx_syn, *p_idx_sem, *p_cn_syn, *p_cn_sem, *p_cl_syn, *p_cl_sem, *p_nsum, *p_loss;
    void *p_maxcn, *p_zbf_syn, *p_zbf_sem, *p_cbf_syn, *p_cbf_sem, *p_cv, *p_ck;
    cudaGetSymbolAddress(&p_esum_syn, g_esum_syn);
    cudaGetSymbolAddress(&p_esum_sem, g_esum_sem);
    cudaGetSymbolAddress(&p_cnt_syn, g_counts_syn);
    cudaGetSymbolAddress(&p_cnt_sem, g_counts_sem);
    cudaGetSymbolAddress(&p_pair_syn, g_pair_syn);
    cudaGetSymbolAddress(&p_pair_sem, g_pair_sem);
    cudaGetSymbolAddress(&p_idx_syn, g_idx_syn);
    cudaGetSymbolAddress(&p_idx_sem, g_idx_sem);
    cudaGetSymbolAddress(&p_cn_syn, g_cnorm_syn);
    cudaGetSymbolAddress(&p_cn_sem, g_cnorm_sem);
    cudaGetSymbolAddress(&p_cl_syn, g_clnew_syn);
    cudaGetSymbolAddress(&p_cl_sem, g_clnew_sem);
    cudaGetSymbolAddress(&p_nsum, g_nsum);
    cudaGetSymbolAddress(&p_loss, g_losspart);
    cudaGetSymbolAddress(&p_maxcn, g_maxcn);
    cudaGetSymbolAddress(&p_zbf_syn, g_zbf_syn);
    cudaGetSymbolAddress(&p_zbf_sem, g_zbf_sem);
    cudaGetSymbolAddress(&p_cbf_syn, g_cbf_syn);
    cudaGetSymbolAddress(&p_cbf_sem, g_cbf_sem);
    cudaGetSymbolAddress(&p_cv, g_cv);
    cudaGetSymbolAddress(&p_ck, g_ck);

    cudaFuncSetAttribute(dist_hmma_kernel,
                         cudaFuncAttributeMaxDynamicSharedMemorySize, SM_TOTAL);

    // 1) zero scratch
    cudaMemsetAsync(p_esum_syn, 0, (size_t)KS * GD * sizeof(float));
    cudaMemsetAsync(p_esum_sem, 0, (size_t)KM * GD * sizeof(float));
    cudaMemsetAsync(p_cnt_syn, 0, KS * sizeof(float));
    cudaMemsetAsync(p_cnt_sem, 0, KM * sizeof(float));
    cudaMemsetAsync(p_pair_syn, 0, (size_t)KS * KS * sizeof(int));
    cudaMemsetAsync(p_pair_sem, 0, (size_t)KM * KM * sizeof(int));
    cudaMemsetAsync(p_nsum, 0, 2 * sizeof(float));
    cudaMemsetAsync(p_loss, 0, 512 * sizeof(float));
    cudaMemsetAsync(p_maxcn, 0, 2 * sizeof(int));

    // 2) conversions (+ fused codebook norms)
    cvt_z_kernel<<<(GN * GD) / 1024, 256>>>(zre_f, zim_f, (__nv_bfloat16*)p_zbf_syn);
    cvt_z_kernel<<<(GN * GD) / 1024, 256>>>(zre_s, zim_s, (__nv_bfloat16*)p_zbf_sem);
    cvt_cb_norm_kernel<<<KS / 2, 256>>>(cb_syn, (__nv_bfloat16*)p_cbf_syn,
                                        (float*)p_cn_syn, (int*)p_maxcn);
    cvt_cb_norm_kernel<<<KM / 2, 256>>>(cb_sem, (__nv_bfloat16*)p_cbf_sem,
                                        (float*)p_cn_sem, ((int*)p_maxcn) + 1);

    // 3) HMMA approximate distance pass (cp.async pipelined)
    dist_hmma_kernel<<<NUNITS, 256, SM_TOTAL>>>(
        (const __nv_bfloat16*)p_zbf_syn, (const __nv_bfloat16*)p_cbf_syn, (const float*)p_cn_syn,
        (const __nv_bfloat16*)p_zbf_sem, (const __nv_bfloat16*)p_cbf_sem, (const float*)p_cn_sem,
        (float*)p_cv, (int*)p_ck);

    // 4) exact fp32 refinement -> final indices
    refine_kernel<<<(2 * GN) / 8, 256>>>(
        zre_f, zim_f, cb_syn, (const float*)p_cn_syn,
        zre_s, zim_s, cb_sem, (const float*)p_cn_sem,
        (const float*)p_cv, (const int*)p_ck, (const int*)p_maxcn,
        (int*)p_idx_syn, (int*)p_idx_sem);

    // 5) fused per-row scatter + zq + loss
    fuse_row_kernel<<<GN, 128>>>(zre_f, zim_f, (const int*)p_idx_syn, prev_syn, cb_syn,
                                 (float*)p_cnt_syn, (float*)p_esum_syn, (int*)p_pair_syn, KS,
                                 out + OFF_ZQ_SYN, out + OFF_IDX_SYN, (float*)p_loss);
    fuse_row_kernel<<<GN, 128>>>(zre_s, zim_s, (const int*)p_idx_sem, prev_sem, cb_sem,
                                 (float*)p_cnt_sem, (float*)p_esum_sem, (int*)p_pair_sem, KM,
                                 out + OFF_ZQ_SEM, out + OFF_IDX_SEM, (float*)p_loss);

    // 6) cluster size EMA + n
    clnew_kernel<<<KS / 256, 256>>>(cl_syn, (const float*)p_cnt_syn,
                                    (float*)p_cl_syn, (float*)p_nsum, KS);
    clnew_kernel<<<KM / 256, 256>>>(cl_sem, (const float*)p_cnt_sem,
                                    (float*)p_cl_sem, ((float*)p_nsum) + 1, KM);

    // 7) codebook EMA update
    cbnew_kernel<<<(KS * GD) / 256, 256>>>(avg_syn, (const float*)p_esum_syn,
                                           (const float*)p_cl_syn, (const float*)p_nsum,
                                           out + OFF_CB_SYN, KS);
    cbnew_kernel<<<(KM * GD) / 256, 256>>>(avg_sem, (const float*)p_esum_sem,
                                           (const float*)p_cl_sem, ((const float*)p_nsum) + 1,
                                           out + OFF_CB_SEM, KM);

    // 8) loss finalize
    finalize_loss_kernel<<<1, 256>>>((const float*)p_loss, out + OFF_LOSS);

    // 9) adjacency transform
    {
        size_t tot = (size_t)KS * KS;
        adj_kernel<<<(unsigned)(tot / 1024), 256>>>(adj_syn, (const int*)p_pair_syn,
                                                    out + OFF_ADJ_SYN, tot);
    }
    {
        size_t tot = (size_t)KM * KM;
        adj_kernel<<<(unsigned)(tot / 1024), 256>>>(adj_sem, (const int*)p_pair_sem,
                                                    out + OFF_ADJ_SEM, tot);
    }
    (void)in_sizes; (void)n_in; (void)out_size;
}

// round 7
// speedup vs baseline: 1.4622x; 1.4622x over previous
#include <cuda_runtime.h>
#include <cuda_bf16.h>
#include <math.h>
#include <float.h>
#include <stdint.h>

// Problem constants
#define GN   32768
#define GLD  256
#define GD   512
#define KS   1024
#define KM   4096
#define NUNITS 1280   // 256 syn units + 1024 sem units (each: 128 rows x 1024 codes)

// ---------------- scratch (static __device__, no allocation) ----------------
static __device__ float g_esum_syn[KS * GD];
static __device__ float g_esum_sem[KM * GD];
static __device__ float g_counts_syn[KS];
static __device__ float g_counts_sem[KM];
static __device__ int   g_pair_syn[(size_t)KS * KS];
static __device__ int   g_pair_sem[(size_t)KM * KM];
static __device__ int   g_idx_syn[GN];
static __device__ int   g_idx_sem[GN];
static __device__ float g_cnorm_syn[KS];
static __device__ float g_cnorm_sem[KM];
static __device__ float g_clnew_syn[KS];
static __device__ float g_clnew_sem[KM];
static __device__ float g_nsum[2];
static __device__ float g_losspart[512];
static __device__ int   g_maxcn[2];   // float-as-int max of squared code norms
// bf16 copies (16B-aligned for uint4 access)
static __device__ __align__(16) __nv_bfloat16 g_zbf_syn[(size_t)GN * GD];
static __device__ __align__(16) __nv_bfloat16 g_zbf_sem[(size_t)GN * GD];
static __device__ __align__(16) __nv_bfloat16 g_cbf_syn[(size_t)KS * GD];
static __device__ __align__(16) __nv_bfloat16 g_cbf_sem[(size_t)KM * GD];
// candidates: per (unit, local row): 32 slots
static __device__ float g_cv[(size_t)NUNITS * 128 * 32];
static __device__ int   g_ck[(size_t)NUNITS * 128 * 32];

// ---------------- PTX helpers (arch-agnostic: ldmatrix + mma.sync) ----------
__device__ __forceinline__ uint32_t smem_u32(const void* p) {
    uint32_t a;
    asm("{ .reg .u64 t; cvta.to.shared.u64 t, %1; cvt.u32.u64 %0, t; }" : "=r"(a) : "l"(p));
    return a;
}
__device__ __forceinline__ void ldsm4(uint32_t& r0, uint32_t& r1, uint32_t& r2, uint32_t& r3,
                                      uint32_t addr) {
    asm volatile("ldmatrix.sync.aligned.m8n8.x4.shared.b16 {%0,%1,%2,%3}, [%4];"
                 : "=r"(r0), "=r"(r1), "=r"(r2), "=r"(r3) : "r"(addr));
}
__device__ __forceinline__ void mma_bf16(float* d, const uint32_t* a, uint32_t b0, uint32_t b1) {
    asm volatile("mma.sync.aligned.m16n8k16.row.col.f32.bf16.bf16.f32 "
                 "{%0,%1,%2,%3}, {%4,%5,%6,%7}, {%8,%9}, {%0,%1,%2,%3};"
                 : "+f"(d[0]), "+f"(d[1]), "+f"(d[2]), "+f"(d[3])
                 : "r"(a[0]), "r"(a[1]), "r"(a[2]), "r"(a[3]), "r"(b0), "r"(b1));
}

// ---------------- generic helpers ----------------
__device__ __forceinline__ float blk_reduce_256(float v) {
    __shared__ float sh[8];
    int lane = threadIdx.x & 31, w = threadIdx.x >> 5;
#pragma unroll
    for (int o = 16; o; o >>= 1) v += __shfl_down_sync(0xffffffffu, v, o);
    if (lane == 0) sh[w] = v;
    __syncthreads();
    if (w == 0) {
        v = (lane < 8) ? sh[lane] : 0.f;
#pragma unroll
        for (int o = 4; o; o >>= 1) v += __shfl_down_sync(0xffffffffu, v, o);
    }
    return v;
}

// ---------------- conversions ----------------
__global__ void cvt_z_kernel(const float* __restrict__ re, const float* __restrict__ im,
                             __nv_bfloat16* __restrict__ out) {
    size_t e = ((size_t)blockIdx.x * 256 + threadIdx.x) * 4;
    int n = (int)(e >> 9), d = (int)(e & 511);
    const float* s = (d < GLD) ? re + (size_t)n * GLD + d : im + (size_t)n * GLD + (d - GLD);
    float4 v = *(const float4*)s;
    __nv_bfloat162 a = __floats2bfloat162_rn(v.x, v.y);
    __nv_bfloat162 b = __floats2bfloat162_rn(v.z, v.w);
    ((__nv_bfloat162*)(out + e))[0] = a;
    ((__nv_bfloat162*)(out + e))[1] = b;
}

// fused codebook convert + per-row squared norms + max
__global__ void cvt_cb_norm_kernel(const float* __restrict__ cb, __nv_bfloat16* __restrict__ out,
                                   float* __restrict__ norms, int* __restrict__ mx) {
    __shared__ float sh[8];
    int t = threadIdx.x, lane = t & 31, w = t >> 5;
    size_t e = ((size_t)blockIdx.x * 256 + t) * 4;
    float4 v = *(const float4*)(cb + e);
    __nv_bfloat162 a = __floats2bfloat162_rn(v.x, v.y);
    __nv_bfloat162 b = __floats2bfloat162_rn(v.z, v.w);
    ((__nv_bfloat162*)(out + e))[0] = a;
    ((__nv_bfloat162*)(out + e))[1] = b;
    float s = v.x * v.x + v.y * v.y + v.z * v.z + v.w * v.w;
#pragma unroll
    for (int o = 16; o; o >>= 1) s += __shfl_xor_sync(0xffffffffu, s, o);
    if (lane == 0) sh[w] = s;
    __syncthreads();
    if (t == 0) {
        float n0 = sh[0] + sh[1] + sh[2] + sh[3];
        norms[blockIdx.x * 2] = n0;
        atomicMax(mx, __float_as_int(n0));
    } else if (t == 128) {
        float n1 = sh[4] + sh[5] + sh[6] + sh[7];
        norms[blockIdx.x * 2 + 1] = n1;
        atomicMax(mx, __float_as_int(n1));
    }
}

// ---------------- HMMA bf16 distance pass (round-4 proven version) ---------
// Per unit (CTA, 256 thr = 8 warps in 2m x 4n): 128 rows x 1024 codes, D=512.
// Z resident in SMEM (128 x 512 bf16, row stride 1040B = 16B skew).
// Codebook streamed in 128 x 64 chunks (row stride 144B), register prefetch.
#define SM_CN   0
#define SM_Z    512
#define SM_C    (512 + 128 * 1040)                 // 133632
#define SM_SV   SM_C
#define SM_SK   (SM_C + 16384)
#define SM_TOTAL (SM_C + 32768)                    // 166400

__global__ __launch_bounds__(256, 1) void dist_hmma_kernel(
    const __nv_bfloat16* __restrict__ zbfA, const __nv_bfloat16* __restrict__ cbfA,
    const float* __restrict__ cnA,
    const __nv_bfloat16* __restrict__ zbfB, const __nv_bfloat16* __restrict__ cbfB,
    const float* __restrict__ cnB,
    float* __restrict__ cvout, int* __restrict__ ckout)
{
    extern __shared__ __align__(16) char smem[];
    float* sCN = (float*)(smem + SM_CN);
    char*  sZ  = smem + SM_Z;
    char*  sC  = smem + SM_C;
    float* sv  = (float*)(smem + SM_SV);
    int*   sk  = (int*)(smem + SM_SK);

    const int tid = threadIdx.x, wid = tid >> 5, lane = tid & 31;
    const int u = blockIdx.x;

    const __nv_bfloat16 *zsrc, *csrc;
    const float* cn;
    int rowBase, kBase;
    if (u < 256) {
        zsrc = zbfA; csrc = cbfA; cn = cnA; rowBase = u * 128; kBase = 0;
    } else {
        int v = u - 256;
        zsrc = zbfB; csrc = cbfB; cn = cnB;
        rowBase = (v >> 2) * 128; kBase = (v & 3) * 1024;
    }

    // load Z tile: 128 rows x 512 bf16
#pragma unroll
    for (int i = 0; i < 32; i++) {
        int c = tid + 256 * i;       // 16B chunk id, 0..8191
        int r = c >> 6, c8 = c & 63;
        uint4 v = *(const uint4*)(zsrc + (((size_t)(rowBase + r)) << 9) + c8 * 8);
        *(uint4*)(sZ + r * 1040 + c8 * 16) = v;
    }

    const int wm = wid >> 2, wn = wid & 3;
    const uint32_t zaddr0 = smem_u32(sZ) + (uint32_t)((wm * 64 + (lane & 15)) * 1040 + (lane >> 4) * 16);
    const uint32_t caddr0 = smem_u32(sC) +
        (uint32_t)((wn * 32 + ((lane >> 4) << 3) + (lane & 7)) * 144 + ((lane >> 3) & 1) * 16);

    float tv[8][2]; int tk[8][2];
#pragma unroll
    for (int i = 0; i < 8; i++)
#pragma unroll
        for (int s = 0; s < 2; s++) { tv[i][s] = FLT_MAX; tk[i][s] = 0; }

    for (int t = 0; t < 8; t++) {
        const int kTile = kBase + t * 128;
        float acc[4][4][4];
#pragma unroll
        for (int mt = 0; mt < 4; mt++)
#pragma unroll
            for (int nt = 0; nt < 4; nt++)
#pragma unroll
                for (int q = 0; q < 4; q++) acc[mt][nt][q] = 0.f;

        uint4 pf[4];
#pragma unroll
        for (int j = 0; j < 4; j++) {
            int c = tid + 256 * j, r = c >> 3, c8 = c & 7;
            pf[j] = *(const uint4*)(csrc + (((size_t)(kTile + r)) << 9) + c8 * 8);
        }
        for (int dc = 0; dc < 8; dc++) {
            __syncthreads();
            if (dc == 0 && tid < 128) sCN[tid] = cn[kTile + tid];
#pragma unroll
            for (int j = 0; j < 4; j++) {
                int c = tid + 256 * j, r = c >> 3, c8 = c & 7;
                *(uint4*)(sC + r * 144 + c8 * 16) = pf[j];
            }
            if (dc < 7) {
#pragma unroll
                for (int j = 0; j < 4; j++) {
                    int c = tid + 256 * j, r = c >> 3, c8 = c & 7;
                    pf[j] = *(const uint4*)(csrc + (((size_t)(kTile + r)) << 9) + (dc + 1) * 64 + c8 * 8);
                }
            }
            __syncthreads();
#pragma unroll
            for (int ks = 0; ks < 4; ks++) {
                uint32_t b[8];
                ldsm4(b[0], b[1], b[2], b[3], caddr0 + ks * 32);
                ldsm4(b[4], b[5], b[6], b[7], caddr0 + 16 * 144 + ks * 32);
                uint32_t a[4][4];
#pragma unroll
                for (int mt = 0; mt < 4; mt++)
                    ldsm4(a[mt][0], a[mt][1], a[mt][2], a[mt][3],
                          zaddr0 + (uint32_t)(mt * 16 * 1040 + (dc * 64 + ks * 16) * 2));
#pragma unroll
                for (int mt = 0; mt < 4; mt++)
#pragma unroll
                    for (int nt = 0; nt < 4; nt++)
                        mma_bf16(acc[mt][nt], a[mt], b[(nt >> 1) * 4 + (nt & 1) * 2],
                                 b[(nt >> 1) * 4 + (nt & 1) * 2 + 1]);
            }
        }
        // epilogue: fold tile into per-thread top-2 per row
#pragma unroll
        for (int mt = 0; mt < 4; mt++)
#pragma unroll
            for (int half = 0; half < 2; half++) {
                int i = mt * 2 + half;
#pragma unroll
                for (int nt = 0; nt < 4; nt++)
#pragma unroll
                    for (int c = 0; c < 2; c++) {
                        int col = wn * 32 + nt * 8 + (lane & 3) * 2 + c;
                        float s = acc[mt][nt][half * 2 + c];
                        float v = fmaf(-2.f, s, sCN[col]);
                        int k = kTile + col;
                        if (v < tv[i][0]) {
                            tv[i][1] = tv[i][0]; tk[i][1] = tk[i][0];
                            tv[i][0] = v; tk[i][0] = k;
                        } else if (v < tv[i][1]) {
                            tv[i][1] = v; tk[i][1] = k;
                        }
                    }
            }
    }

    // stage candidates in SMEM (overwrites sC region), then coalesced store
    __syncthreads();
#pragma unroll
    for (int i = 0; i < 8; i++) {
        int r = wm * 64 + (i >> 1) * 16 + (i & 1) * 8 + (lane >> 2);
        int slot0 = wn * 8 + (lane & 3) * 2;
#pragma unroll
        for (int s = 0; s < 2; s++) {
            sv[r * 32 + slot0 + s] = tv[i][s];
            sk[r * 32 + slot0 + s] = tk[i][s];
        }
    }
    __syncthreads();
#pragma unroll
    for (int j = 0; j < 16; j++) {
        int idx = tid + 256 * j;
        cvout[(size_t)u * 4096 + idx] = sv[idx];
        ckout[(size_t)u * 4096 + idx] = sk[idx];
    }
}

// ---------------- exact fp32 refinement ----------------
__global__ __launch_bounds__(256) void refine_kernel(
    const float* __restrict__ zreA, const float* __restrict__ zimA,
    const float* __restrict__ cbA, const float* __restrict__ cnA,
    const float* __restrict__ zreB, const float* __restrict__ zimB,
    const float* __restrict__ cbB, const float* __restrict__ cnB,
    const float* __restrict__ cv, const int* __restrict__ ck,
    const int* __restrict__ maxcn,
    int* __restrict__ idxA, int* __restrict__ idxB)
{
    int wid = threadIdx.x >> 5, lane = threadIdx.x & 31;
    int gw = blockIdx.x * 8 + wid;
    int n = gw >> 1, cbk = gw & 1;
    const float *zre, *zim, *cb, *cn;
    int* idxo;
    int cnt;
    size_t base;
    if (cbk == 0) {
        zre = zreA; zim = zimA; cb = cbA; cn = cnA; idxo = idxA;
        cnt = 32; base = ((size_t)(n >> 7) * 128 + (n & 127)) * 32;
    } else {
        zre = zreB; zim = zimB; cb = cbB; cn = cnB; idxo = idxB;
        cnt = 128; base = ((size_t)(256 + (n >> 7) * 4) * 128 + (n & 127)) * 32;
    }

    float zr[16];
    float zn2 = 0.f;
#pragma unroll
    for (int j = 0; j < 16; j++) {
        int d = lane + 32 * j;
        float z = (d < GLD) ? zre[(size_t)n * GLD + d] : zim[(size_t)n * GLD + d - GLD];
        zr[j] = z;
        zn2 = fmaf(z, z, zn2);
    }
#pragma unroll
    for (int o = 16; o; o >>= 1) zn2 += __shfl_xor_sync(0xffffffffu, zn2, o);

    float vb = FLT_MAX;
    for (int c = lane; c < cnt; c += 32) {
        float v = cv[base + (size_t)(c >> 5) * 4096 + (c & 31)];
        vb = fminf(vb, v);
    }
#pragma unroll
    for (int o = 16; o; o >>= 1) vb = fminf(vb, __shfl_xor_sync(0xffffffffu, vb, o));

    float maxc2 = __int_as_float(maxcn[cbk]);
    float vlim = vb + 0.03125f * sqrtf(zn2 * maxc2) + 0.125f;

    float bd = FLT_MAX; int bk = 0x7fffffff;
    for (int i = 0; i < cnt; i++) {
        size_t a = base + (size_t)(i >> 5) * 4096 + (i & 31);
        float v = cv[a];
        if (v <= vlim) {
            int k = ck[a];
            const float* crow = cb + (size_t)k * GD;
            float s = 0.f;
#pragma unroll
            for (int j = 0; j < 16; j++) s = fmaf(zr[j], crow[lane + 32 * j], s);
#pragma unroll
            for (int o = 16; o; o >>= 1) s += __shfl_xor_sync(0xffffffffu, s, o);
            float d = fmaf(-2.f, s, cn[k]);
            if (d < bd || (d == bd && k < bk)) { bd = d; bk = k; }
        }
    }
    if (lane == 0) idxo[n] = bk;
}

// ---- fused per-row: counts/pair scatter + esum scatter + zq write + loss ----
__global__ __launch_bounds__(128) void fuse_row_kernel(
    const float* __restrict__ zre, const float* __restrict__ zim,
    const int* __restrict__ idx, const int* __restrict__ prev,
    const float* __restrict__ cb,
    float* __restrict__ counts, float* __restrict__ esum, int* __restrict__ pair, int K,
    float* __restrict__ zq, float* __restrict__ idxf, float* __restrict__ lossPart)
{
    __shared__ float sh[4];
    int n = blockIdx.x, t = threadIdx.x;
    int lane = t & 31, w = t >> 5;
    int i = idx[n];
    if (t == 0) {
        atomicAdd(&counts[i], 1.f);
        atomicAdd(&pair[(size_t)prev[n] * K + i], 1);
        idxf[n] = (float)i;
    }
    int d = t * 4;
    const float* zsrc = (d < GLD) ? zre + (size_t)n * GLD + d
                                  : zim + (size_t)n * GLD + (d - GLD);
    float4 z = *(const float4*)zsrc;
    float4 q = *(const float4*)(cb + (size_t)i * GD + d);
    *(float4*)(zq + (size_t)n * GD + d) = q;
    float dx = q.x - z.x, dy = q.y - z.y, dz = q.z - z.z, dw = q.w - z.w;
    float s = dx * dx + dy * dy + dz * dz + dw * dw;
    float* es = esum + (size_t)i * GD + d;
    atomicAdd(es + 0, z.x);
    atomicAdd(es + 1, z.y);
    atomicAdd(es + 2, z.z);
    atomicAdd(es + 3, z.w);
#pragma unroll
    for (int o = 16; o; o >>= 1) s += __shfl_down_sync(0xffffffffu, s, o);
    if (lane == 0) sh[w] = s;
    __syncthreads();
    if (t == 0) atomicAdd(&lossPart[n & 511], sh[0] + sh[1] + sh[2] + sh[3]);
}

// ---------------- cluster_size EMA + n reduction ----------------
__global__ void clnew_kernel(const float* __restrict__ cl, const float* __restrict__ counts,
                             float* __restrict__ clnew, float* __restrict__ nsum, int K)
{
    int k = blockIdx.x * 256 + threadIdx.x;
    float v = 0.f;
    if (k < K) {
        v = cl[k] * 0.99f + 0.01f * counts[k];
        clnew[k] = v;
    }
    v = blk_reduce_256(v);
    if (threadIdx.x == 0) atomicAdd(nsum, v);
}

// ---------------- codebook EMA update ----------------
__global__ void cbnew_kernel(const float* __restrict__ avg, const float* __restrict__ esum,
                             const float* __restrict__ clnew, const float* __restrict__ nsum,
                             float* __restrict__ out, int K)
{
    size_t idx = (size_t)blockIdx.x * 256 + threadIdx.x;
    int k = (int)(idx >> 9);
    float n = *nsum;
    float cs = (clnew[k] + 1e-6f) / (n + (float)K * 1e-6f) * n;
    float a = avg[idx] * 0.99f + 0.01f * esum[idx];
    out[idx] = a / cs;
}

__global__ void finalize_loss_kernel(const float* __restrict__ lacc, float* __restrict__ out) {
    __shared__ float sh[8];
    int t = threadIdx.x, lane = t & 31, w = t >> 5;
    float s = lacc[t] + lacc[t + 256];
#pragma unroll
    for (int o = 16; o; o >>= 1) s += __shfl_down_sync(0xffffffffu, s, o);
    if (lane == 0) sh[w] = s;
    __syncthreads();
    if (t == 0) {
        float v = 0.f;
#pragma unroll
        for (int j = 0; j < 8; j++) v += sh[j];
        out[0] = 1.25f * v / 16777216.f;
    }
}

// ---------------- adjacency transform (vector loads, scalar stores) --------
// NOTE: out may be only 4B-aligned (odd element offset in d_out) — scalar STG.
__device__ __forceinline__ float adj1(float a, int c) {
    if (c == 0) return a;
    float p = powf(0.99f, (float)c);
    return fmaf(a, p, (1.f - p) * 100.f);
}
__global__ void adj_kernel(const float* __restrict__ adj, const int* __restrict__ cnt,
                           float* __restrict__ out, size_t total)
{
    size_t i = ((size_t)blockIdx.x * 256 + threadIdx.x) * 4;
    if (i >= total) return;
    int4 c = *(const int4*)(cnt + i);
    float4 a = *(const float4*)(adj + i);
    out[i + 0] = adj1(a.x, c.x);
    out[i + 1] = adj1(a.y, c.y);
    out[i + 2] = adj1(a.z, c.z);
    out[i + 3] = adj1(a.w, c.w);
}

// ---------------- launch ----------------
extern "C" void kernel_launch(void* const* d_in, const int* in_sizes, int n_in,
                              void* d_out, int out_size)
{
    const float* zre_f = (const float*)d_in[0];
    const float* zim_f = (const float*)d_in[1];
    const float* zre_s = (const float*)d_in[2];
    const float* zim_s = (const float*)d_in[3];
    const int*   prev_syn = (const int*)d_in[4];
    const int*   prev_sem = (const int*)d_in[5];
    const float* cb_syn = (const float*)d_in[6];
    const float* cb_sem = (const float*)d_in[7];
    const float* cl_syn = (const float*)d_in[8];
    const float* avg_syn = (const float*)d_in[9];
    const float* cl_sem = (const float*)d_in[10];
    const float* avg_sem = (const float*)d_in[11];
    const float* adj_syn = (const float*)d_in[12];
    const float* adj_sem = (const float*)d_in[13];

    float* out = (float*)d_out;
    const size_t OFF_ZQ_SYN = 0;
    const size_t OFF_ZQ_SEM = OFF_ZQ_SYN + (size_t)GN * GD;
    const size_t OFF_LOSS   = OFF_ZQ_SEM + (size_t)GN * GD;
    const size_t OFF_IDX_SYN = OFF_LOSS + 1;
    const size_t OFF_IDX_SEM = OFF_IDX_SYN + GN;
    const size_t OFF_CB_SYN  = OFF_IDX_SEM + GN;
    const size_t OFF_CB_SEM  = OFF_CB_SYN + (size_t)KS * GD;
    const size_t OFF_ADJ_SYN = OFF_CB_SEM + (size_t)KM * GD;
    const size_t OFF_ADJ_SEM = OFF_ADJ_SYN + (size_t)KS * KS;

    void *p_esum_syn, *p_esum_sem, *p_cnt_syn, *p_cnt_sem, *p_pair_syn, *p_pair_sem;
    void *p_idx_syn, *p_idx_sem, *p_cn_syn, *p_cn_sem, *p_cl_syn, *p_cl_sem, *p_nsum, *p_loss;
    void *p_maxcn, *p_zbf_syn, *p_zbf_sem, *p_cbf_syn, *p_cbf_sem, *p_cv, *p_ck;
    cudaGetSymbolAddress(&p_esum_syn, g_esum_syn);
    cudaGetSymbolAddress(&p_esum_sem, g_esum_sem);
    cudaGetSymbolAddress(&p_cnt_syn, g_counts_syn);
    cudaGetSymbolAddress(&p_cnt_sem, g_counts_sem);
    cudaGetSymbolAddress(&p_pair_syn, g_pair_syn);
    cudaGetSymbolAddress(&p_pair_sem, g_pair_sem);
    cudaGetSymbolAddress(&p_idx_syn, g_idx_syn);
    cudaGetSymbolAddress(&p_idx_sem, g_idx_sem);
    cudaGetSymbolAddress(&p_cn_syn, g_cnorm_syn);
    cudaGetSymbolAddress(&p_cn_sem, g_cnorm_sem);
    cudaGetSymbolAddress(&p_cl_syn, g_clnew_syn);
    cudaGetSymbolAddress(&p_cl_sem, g_clnew_sem);
    cudaGetSymbolAddress(&p_nsum, g_nsum);
    cudaGetSymbolAddress(&p_loss, g_losspart);
    cudaGetSymbolAddress(&p_maxcn, g_maxcn);
    cudaGetSymbolAddress(&p_zbf_syn, g_zbf_syn);
    cudaGetSymbolAddress(&p_zbf_sem, g_zbf_sem);
    cudaGetSymbolAddress(&p_cbf_syn, g_cbf_syn);
    cudaGetSymbolAddress(&p_cbf_sem, g_cbf_sem);
    cudaGetSymbolAddress(&p_cv, g_cv);
    cudaGetSymbolAddress(&p_ck, g_ck);

    cudaFuncSetAttribute(dist_hmma_kernel,
                         cudaFuncAttributeMaxDynamicSharedMemorySize, SM_TOTAL);

    // 1) zero scratch
    cudaMemsetAsync(p_esum_syn, 0, (size_t)KS * GD * sizeof(float));
    cudaMemsetAsync(p_esum_sem, 0, (size_t)KM * GD * sizeof(float));
    cudaMemsetAsync(p_cnt_syn, 0, KS * sizeof(float));
    cudaMemsetAsync(p_cnt_sem, 0, KM * sizeof(float));
    cudaMemsetAsync(p_pair_syn, 0, (size_t)KS * KS * sizeof(int));
    cudaMemsetAsync(p_pair_sem, 0, (size_t)KM * KM * sizeof(int));
    cudaMemsetAsync(p_nsum, 0, 2 * sizeof(float));
    cudaMemsetAsync(p_loss, 0, 512 * sizeof(float));
    cudaMemsetAsync(p_maxcn, 0, 2 * sizeof(int));

    // 2) conversions (+ fused codebook norms)
    cvt_z_kernel<<<(GN * GD) / 1024, 256>>>(zre_f, zim_f, (__nv_bfloat16*)p_zbf_syn);
    cvt_z_kernel<<<(GN * GD) / 1024, 256>>>(zre_s, zim_s, (__nv_bfloat16*)p_zbf_sem);
    cvt_cb_norm_kernel<<<KS / 2, 256>>>(cb_syn, (__nv_bfloat16*)p_cbf_syn,
                                        (float*)p_cn_syn, (int*)p_maxcn);
    cvt_cb_norm_kernel<<<KM / 2, 256>>>(cb_sem, (__nv_bfloat16*)p_cbf_sem,
                                        (float*)p_cn_sem, ((int*)p_maxcn) + 1);

    // 3) HMMA approximate distance pass
    dist_hmma_kernel<<<NUNITS, 256, SM_TOTAL>>>(
        (const __nv_bfloat16*)p_zbf_syn, (const __nv_bfloat16*)p_cbf_syn, (const float*)p_cn_syn,
        (const __nv_bfloat16*)p_zbf_sem, (const __nv_bfloat16*)p_cbf_sem, (const float*)p_cn_sem,
        (float*)p_cv, (int*)p_ck);

    // 4) exact fp32 refinement -> final indices
    refine_kernel<<<(2 * GN) / 8, 256>>>(
        zre_f, zim_f, cb_syn, (const float*)p_cn_syn,
        zre_s, zim_s, cb_sem, (const float*)p_cn_sem,
        (const float*)p_cv, (const int*)p_ck, (const int*)p_maxcn,
        (int*)p_idx_syn, (int*)p_idx_sem);

    // 5) fused per-row scatter + zq + loss
    fuse_row_kernel<<<GN, 128>>>(zre_f, zim_f, (const int*)p_idx_syn, prev_syn, cb_syn,
                                 (float*)p_cnt_syn, (float*)p_esum_syn, (int*)p_pair_syn, KS,
                                 out + OFF_ZQ_SYN, out + OFF_IDX_SYN, (float*)p_loss);
    fuse_row_kernel<<<GN, 128>>>(zre_s, zim_s, (const int*)p_idx_sem, prev_sem, cb_sem,
                                 (float*)p_cnt_sem, (float*)p_esum_sem, (int*)p_pair_sem, KM,
                                 out + OFF_ZQ_SEM, out + OFF_IDX_SEM, (float*)p_loss);

    // 6) cluster size EMA + n
    clnew_kernel<<<KS / 256, 256>>>(cl_syn, (const float*)p_cnt_syn,
                                    (float*)p_cl_syn, (float*)p_nsum, KS);
    clnew_kernel<<<KM / 256, 256>>>(cl_sem, (const float*)p_cnt_sem,
                                    (float*)p_cl_sem, ((float*)p_nsum) + 1, KM);

    // 7) codebook EMA update
    cbnew_kernel<<<(KS * GD) / 256, 256>>>(avg_syn, (const float*)p_esum_syn,
                                           (const float*)p_cl_syn, (const float*)p_nsum,
                                           out + OFF_CB_SYN, KS);
    cbnew_kernel<<<(KM * GD) / 256, 256>>>(avg_sem, (const float*)p_esum_sem,
                                           (const float*)p_cl_sem, ((const float*)p_nsum) + 1,
                                           out + OFF_CB_SEM, KM);

    // 8) loss finalize
    finalize_loss_kernel<<<1, 256>>>((const float*)p_loss, out + OFF_LOSS);

    // 9) adjacency transform
    {
        size_t tot = (size_t)KS * KS;
        adj_kernel<<<(unsigned)(tot / 1024), 256>>>(adj_syn, (const int*)p_pair_syn,
                                                    out + OFF_ADJ_SYN, tot);
    }
    {
        size_t tot = (size_t)KM * KM;
        adj_kernel<<<(unsigned)(tot / 1024), 256>>>(adj_sem, (const int*)p_pair_sem,
                                                    out + OFF_ADJ_SEM, tot);
    }
    (void)in_sizes; (void)n_in; (void)out_size;
}

// round 9
// speedup vs baseline: 1.4675x; 1.0037x over previous
#include <cuda_runtime.h>
#include <cuda_bf16.h>
#include <math.h>
#include <float.h>
#include <stdint.h>

// Problem constants
#define GN   32768
#define GLD  256
#define GD   512
#define KS   1024
#define KM   4096
#define NUNITS 1280   // 256 syn units + 1024 sem units (each: 128 rows x 1024 codes)

// ---------------- scratch (static __device__, no allocation) ----------------
static __device__ float g_esum_syn[KS * GD];
static __device__ float g_esum_sem[KM * GD];
static __device__ float g_counts_syn[KS];
static __device__ float g_counts_sem[KM];
static __device__ int   g_pair_syn[(size_t)KS * KS];
static __device__ int   g_pair_sem[(size_t)KM * KM];
static __device__ int   g_idx_syn[GN];
static __device__ int   g_idx_sem[GN];
static __device__ float g_cnorm_syn[KS];
static __device__ float g_cnorm_sem[KM];
static __device__ float g_clnew_syn[KS];
static __device__ float g_clnew_sem[KM];
static __device__ float g_nsum[2];
static __device__ float g_losspart[512];
static __device__ int   g_maxcn[2];   // float-as-int max of squared code norms
// bf16 copies (16B-aligned for uint4 access)
static __device__ __align__(16) __nv_bfloat16 g_zbf_syn[(size_t)GN * GD];
static __device__ __align__(16) __nv_bfloat16 g_zbf_sem[(size_t)GN * GD];
static __device__ __align__(16) __nv_bfloat16 g_cbf_syn[(size_t)KS * GD];
static __device__ __align__(16) __nv_bfloat16 g_cbf_sem[(size_t)KM * GD];
// candidates: per (unit, local row): 32 slots
static __device__ float g_cv[(size_t)NUNITS * 128 * 32];
static __device__ int   g_ck[(size_t)NUNITS * 128 * 32];

// ---------------- PTX helpers (arch-agnostic: ldmatrix + mma.sync) ----------
__device__ __forceinline__ uint32_t smem_u32(const void* p) {
    uint32_t a;
    asm("{ .reg .u64 t; cvta.to.shared.u64 t, %1; cvt.u32.u64 %0, t; }" : "=r"(a) : "l"(p));
    return a;
}
__device__ __forceinline__ void ldsm4(uint32_t& r0, uint32_t& r1, uint32_t& r2, uint32_t& r3,
                                      uint32_t addr) {
    asm volatile("ldmatrix.sync.aligned.m8n8.x4.shared.b16 {%0,%1,%2,%3}, [%4];"
                 : "=r"(r0), "=r"(r1), "=r"(r2), "=r"(r3) : "r"(addr));
}
__device__ __forceinline__ void mma_bf16(float* d, const uint32_t* a, uint32_t b0, uint32_t b1) {
    asm volatile("mma.sync.aligned.m16n8k16.row.col.f32.bf16.bf16.f32 "
                 "{%0,%1,%2,%3}, {%4,%5,%6,%7}, {%8,%9}, {%0,%1,%2,%3};"
                 : "+f"(d[0]), "+f"(d[1]), "+f"(d[2]), "+f"(d[3])
                 : "r"(a[0]), "r"(a[1]), "r"(a[2]), "r"(a[3]), "r"(b0), "r"(b1));
}

// ---------------- generic helpers ----------------
__device__ __forceinline__ float blk_reduce_256(float v) {
    __shared__ float sh[8];
    int lane = threadIdx.x & 31, w = threadIdx.x >> 5;
#pragma unroll
    for (int o = 16; o; o >>= 1) v += __shfl_down_sync(0xffffffffu, v, o);
    if (lane == 0) sh[w] = v;
    __syncthreads();
    if (w == 0) {
        v = (lane < 8) ? sh[lane] : 0.f;
#pragma unroll
        for (int o = 4; o; o >>= 1) v += __shfl_down_sync(0xffffffffu, v, o);
    }
    return v;
}

// ---------------- conversions ----------------
__global__ void cvt_z_kernel(const float* __restrict__ re, const float* __restrict__ im,
                             __nv_bfloat16* __restrict__ out) {
    size_t e = ((size_t)blockIdx.x * 256 + threadIdx.x) * 4;
    int n = (int)(e >> 9), d = (int)(e & 511);
    const float* s = (d < GLD) ? re + (size_t)n * GLD + d : im + (size_t)n * GLD + (d - GLD);
    float4 v = *(const float4*)s;
    __nv_bfloat162 a = __floats2bfloat162_rn(v.x, v.y);
    __nv_bfloat162 b = __floats2bfloat162_rn(v.z, v.w);
    ((__nv_bfloat162*)(out + e))[0] = a;
    ((__nv_bfloat162*)(out + e))[1] = b;
}

// fused codebook convert + per-row squared norms + max
__global__ void cvt_cb_norm_kernel(const float* __restrict__ cb, __nv_bfloat16* __restrict__ out,
                                   float* __restrict__ norms, int* __restrict__ mx) {
    __shared__ float sh[8];
    int t = threadIdx.x, lane = t & 31, w = t >> 5;
    size_t e = ((size_t)blockIdx.x * 256 + t) * 4;
    float4 v = *(const float4*)(cb + e);
    __nv_bfloat162 a = __floats2bfloat162_rn(v.x, v.y);
    __nv_bfloat162 b = __floats2bfloat162_rn(v.z, v.w);
    ((__nv_bfloat162*)(out + e))[0] = a;
    ((__nv_bfloat162*)(out + e))[1] = b;
    float s = v.x * v.x + v.y * v.y + v.z * v.z + v.w * v.w;
#pragma unroll
    for (int o = 16; o; o >>= 1) s += __shfl_xor_sync(0xffffffffu, s, o);
    if (lane == 0) sh[w] = s;
    __syncthreads();
    if (t == 0) {
        float n0 = sh[0] + sh[1] + sh[2] + sh[3];
        norms[blockIdx.x * 2] = n0;
        atomicMax(mx, __float_as_int(n0));
    } else if (t == 128) {
        float n1 = sh[4] + sh[5] + sh[6] + sh[7];
        norms[blockIdx.x * 2 + 1] = n1;
        atomicMax(mx, __float_as_int(n1));
    }
}

// ---------------- HMMA bf16 distance pass (4-stage LDG/STS pipeline) -------
// Per unit (CTA, 256 thr = 8 warps in 2m x 4n): 128 rows x 1024 codes, D=512.
// Z resident in SMEM (128 x 512 bf16, row stride 1040B = 16B skew).
// Codebook streamed as 64 chunks (128 codes x 64 d, row stride 144B),
// 4 SMEM stages + 2 prefetch register sets -> 2-iteration LDG->STS distance,
// ONE __syncthreads per chunk.
#define SM_Z      0
#define SM_C      133120
#define SM_STAGE  18432
#define SM_TOTAL  (SM_C + 4 * SM_STAGE)   // 206848
#define SM_SV     SM_C
#define SM_SK     (SM_C + 16384)

__global__ __launch_bounds__(256, 1) void dist_hmma_kernel(
    const __nv_bfloat16* __restrict__ zbfA, const __nv_bfloat16* __restrict__ cbfA,
    const float* __restrict__ cnA,
    const __nv_bfloat16* __restrict__ zbfB, const __nv_bfloat16* __restrict__ cbfB,
    const float* __restrict__ cnB,
    float* __restrict__ cvout, int* __restrict__ ckout)
{
    extern __shared__ __align__(16) char smem[];
    char* sZ = smem + SM_Z;
    const uint32_t sbase = smem_u32(smem);

    const int tid = threadIdx.x, wid = tid >> 5, lane = tid & 31;
    const int u = blockIdx.x;

    const __nv_bfloat16 *zsrc, *csrc;
    const float* cn;
    int rowBase, kBase;
    if (u < 256) {
        zsrc = zbfA; csrc = cbfA; cn = cnA; rowBase = u * 128; kBase = 0;
    } else {
        int v = u - 256;
        zsrc = zbfB; csrc = cbfB; cn = cnB;
        rowBase = (v >> 2) * 128; kBase = (v & 3) * 1024;
    }

    // load Z tile: 128 rows x 512 bf16
#pragma unroll
    for (int i = 0; i < 32; i++) {
        int c = tid + 256 * i;       // 16B chunk id, 0..8191
        int r = c >> 6, c8 = c & 63;
        uint4 v = *(const uint4*)(zsrc + (((size_t)(rowBase + r)) << 9) + c8 * 8);
        *(uint4*)(sZ + r * 1040 + c8 * 16) = v;
    }

    const int wm = wid >> 2, wn = wid & 3;
    const uint32_t zaddr0 = sbase + SM_Z +
        (uint32_t)((wm * 64 + (lane & 15)) * 1040 + (lane >> 4) * 16);
    const uint32_t coff = (uint32_t)((wn * 32 + ((lane >> 4) << 3) + (lane & 7)) * 144 +
                                     ((lane >> 3) & 1) * 16);

    float tv[8][2]; int tk[8][2];
#pragma unroll
    for (int i = 0; i < 8; i++)
#pragma unroll
        for (int s = 0; s < 2; s++) { tv[i][s] = FLT_MAX; tk[i][s] = 0; }

    float acc[4][4][4];
#pragma unroll
    for (int mt = 0; mt < 4; mt++)
#pragma unroll
        for (int nt = 0; nt < 4; nt++)
#pragma unroll
            for (int q = 0; q < 4; q++) acc[mt][nt][q] = 0.f;

    // load chunk cc of the codebook stream into a register set
#define LDGC(pf, cc) do { \
        int _t = (cc) >> 3, _dc = (cc) & 7; \
        _Pragma("unroll") \
        for (int _j = 0; _j < 4; _j++) { \
            int _id = tid + 256 * _j; int _r = _id >> 3, _c8 = _id & 7; \
            (pf)[_j] = *(const uint4*)(csrc + (((size_t)(kBase + _t * 128 + _r)) << 9) \
                                       + _dc * 64 + _c8 * 8); \
        } \
    } while (0)
    // store a register set into stage buffer (cc & 3)
#define STSC(pf, cc) do { \
        char* _sp = smem + SM_C + ((cc) & 3) * SM_STAGE; \
        _Pragma("unroll") \
        for (int _j = 0; _j < 4; _j++) { \
            int _id = tid + 256 * _j; int _r = _id >> 3, _c8 = _id & 7; \
            *(uint4*)(_sp + _r * 144 + _c8 * 16) = (pf)[_j]; \
        } \
    } while (0)

    uint4 pfA[4], pfB[4];
    // prologue: fill buf0,buf1; prefetch chunks 2,3 into regs
    LDGC(pfA, 0); LDGC(pfB, 1);
    STSC(pfA, 0); LDGC(pfA, 2);
    STSC(pfB, 1); LDGC(pfB, 3);
    __syncthreads();

    for (int c = 0; c < 64; c++) {
        // stage chunk c+2 (held in pf[c&1]); prefetch chunk c+4
        if (c + 2 < 64) {
            if (c & 1) { STSC(pfB, c + 2); if (c + 4 < 64) LDGC(pfB, c + 4); }
            else       { STSC(pfA, c + 2); if (c + 4 < 64) LDGC(pfA, c + 4); }
        }

        // compute chunk c from buf[c&3]
        const int dc = c & 7;
        const uint32_t caddr0 = sbase + (uint32_t)(SM_C + (c & 3) * SM_STAGE) + coff;
#pragma unroll
        for (int ks = 0; ks < 4; ks++) {
            uint32_t b[8];
            ldsm4(b[0], b[1], b[2], b[3], caddr0 + ks * 32);
            ldsm4(b[4], b[5], b[6], b[7], caddr0 + 16 * 144 + ks * 32);
            uint32_t a[4][4];
#pragma unroll
            for (int mt = 0; mt < 4; mt++)
                ldsm4(a[mt][0], a[mt][1], a[mt][2], a[mt][3],
                      zaddr0 + (uint32_t)(mt * 16 * 1040 + (dc * 64 + ks * 16) * 2));
#pragma unroll
            for (int mt = 0; mt < 4; mt++)
#pragma unroll
                for (int nt = 0; nt < 4; nt++)
                    mma_bf16(acc[mt][nt], a[mt], b[(nt >> 1) * 4 + (nt & 1) * 2],
                             b[(nt >> 1) * 4 + (nt & 1) * 2 + 1]);
        }

        if (dc == 7) {
            // epilogue: fold tile into per-thread top-2 per row
            const int kTile = kBase + (c >> 3) * 128;
            float cnv[8];
#pragma unroll
            for (int nt = 0; nt < 4; nt++)
#pragma unroll
                for (int cc2 = 0; cc2 < 2; cc2++)
                    cnv[nt * 2 + cc2] = __ldg(&cn[kTile + wn * 32 + nt * 8 + (lane & 3) * 2 + cc2]);
#pragma unroll
            for (int mt = 0; mt < 4; mt++)
#pragma unroll
                for (int half = 0; half < 2; half++) {
                    int i = mt * 2 + half;
#pragma unroll
                    for (int nt = 0; nt < 4; nt++)
#pragma unroll
                        for (int cc2 = 0; cc2 < 2; cc2++) {
                            int col = wn * 32 + nt * 8 + (lane & 3) * 2 + cc2;
                            float s = acc[mt][nt][half * 2 + cc2];
                            float v = fmaf(-2.f, s, cnv[nt * 2 + cc2]);
                            int k = kTile + col;
                            if (v < tv[i][0]) {
                                tv[i][1] = tv[i][0]; tk[i][1] = tk[i][0];
                                tv[i][0] = v; tk[i][0] = k;
                            } else if (v < tv[i][1]) {
                                tv[i][1] = v; tk[i][1] = k;
                            }
                        }
                }
#pragma unroll
            for (int mt = 0; mt < 4; mt++)
#pragma unroll
                for (int nt = 0; nt < 4; nt++)
#pragma unroll
                    for (int q = 0; q < 4; q++) acc[mt][nt][q] = 0.f;
        }
        __syncthreads();
    }

    // stage candidates in SMEM (reuse stage area), then coalesced store
    float* sv = (float*)(smem + SM_SV);
    int*   sk = (int*)(smem + SM_SK);
#pragma unroll
    for (int i = 0; i < 8; i++) {
        int r = wm * 64 + (i >> 1) * 16 + (i & 1) * 8 + (lane >> 2);
        int slot0 = wn * 8 + (lane & 3) * 2;
#pragma unroll
        for (int s = 0; s < 2; s++) {
            sv[r * 32 + slot0 + s] = tv[i][s];
            sk[r * 32 + slot0 + s] = tk[i][s];
        }
    }
    __syncthreads();
#pragma unroll
    for (int j = 0; j < 16; j++) {
        int idx = tid + 256 * j;
        cvout[(size_t)u * 4096 + idx] = sv[idx];
        ckout[(size_t)u * 4096 + idx] = sk[idx];
    }
#undef LDGC
#undef STSC
}

// ---------------- exact fp32 refinement ----------------
__global__ __launch_bounds__(256) void refine_kernel(
    const float* __restrict__ zreA, const float* __restrict__ zimA,
    const float* __restrict__ cbA, const float* __restrict__ cnA,
    const float* __restrict__ zreB, const float* __restrict__ zimB,
    const float* __restrict__ cbB, const float* __restrict__ cnB,
    const float* __restrict__ cv, const int* __restrict__ ck,
    const int* __restrict__ maxcn,
    int* __restrict__ idxA, int* __restrict__ idxB)
{
    int wid = threadIdx.x >> 5, lane = threadIdx.x & 31;
    int gw = blockIdx.x * 8 + wid;
    int n = gw >> 1, cbk = gw & 1;
    const float *zre, *zim, *cb, *cn;
    int* idxo;
    int cnt;
    size_t base;
    if (cbk == 0) {
        zre = zreA; zim = zimA; cb = cbA; cn = cnA; idxo = idxA;
        cnt = 32; base = ((size_t)(n >> 7) * 128 + (n & 127)) * 32;
    } else {
        zre = zreB; zim = zimB; cb = cbB; cn = cnB; idxo = idxB;
        cnt = 128; base = ((size_t)(256 + (n >> 7) * 4) * 128 + (n & 127)) * 32;
    }

    float zr[16];
    float zn2 = 0.f;
#pragma unroll
    for (int j = 0; j < 16; j++) {
        int d = lane + 32 * j;
        float z = (d < GLD) ? zre[(size_t)n * GLD + d] : zim[(size_t)n * GLD + d - GLD];
        zr[j] = z;
        zn2 = fmaf(z, z, zn2);
    }
#pragma unroll
    for (int o = 16; o; o >>= 1) zn2 += __shfl_xor_sync(0xffffffffu, zn2, o);

    float vb = FLT_MAX;
    for (int c = lane; c < cnt; c += 32) {
        float v = cv[base + (size_t)(c >> 5) * 4096 + (c & 31)];
        vb = fminf(vb, v);
    }
#pragma unroll
    for (int o = 16; o; o >>= 1) vb = fminf(vb, __shfl_xor_sync(0xffffffffu, vb, o));

    float maxc2 = __int_as_float(maxcn[cbk]);
    float vlim = vb + 0.03125f * sqrtf(zn2 * maxc2) + 0.125f;

    float bd = FLT_MAX; int bk = 0x7fffffff;
    for (int i = 0; i < cnt; i++) {
        size_t a = base + (size_t)(i >> 5) * 4096 + (i & 31);
        float v = cv[a];
        if (v <= vlim) {
            int k = ck[a];
            const float* crow = cb + (size_t)k * GD;
            float s = 0.f;
#pragma unroll
            for (int j = 0; j < 16; j++) s = fmaf(zr[j], crow[lane + 32 * j], s);
#pragma unroll
            for (int o = 16; o; o >>= 1) s += __shfl_xor_sync(0xffffffffu, s, o);
            float d = fmaf(-2.f, s, cn[k]);
            if (d < bd || (d == bd && k < bk)) { bd = d; bk = k; }
        }
    }
    if (lane == 0) idxo[n] = bk;
}

// ---- fused per-row: counts/pair scatter + esum scatter + zq write + loss ----
__global__ __launch_bounds__(128) void fuse_row_kernel(
    const float* __restrict__ zre, const float* __restrict__ zim,
    const int* __restrict__ idx, const int* __restrict__ prev,
    const float* __restrict__ cb,
    float* __restrict__ counts, float* __restrict__ esum, int* __restrict__ pair, int K,
    float* __restrict__ zq, float* __restrict__ idxf, float* __restrict__ lossPart)
{
    __shared__ float sh[4];
    int n = blockIdx.x, t = threadIdx.x;
    int lane = t & 31, w = t >> 5;
    int i = idx[n];
    if (t == 0) {
        atomicAdd(&counts[i], 1.f);
        atomicAdd(&pair[(size_t)prev[n] * K + i], 1);
        idxf[n] = (float)i;
    }
    int d = t * 4;
    const float* zsrc = (d < GLD) ? zre + (size_t)n * GLD + d
                                  : zim + (size_t)n * GLD + (d - GLD);
    float4 z = *(const float4*)zsrc;
    float4 q = *(const float4*)(cb + (size_t)i * GD + d);
    *(float4*)(zq + (size_t)n * GD + d) = q;
    float dx = q.x - z.x, dy = q.y - z.y, dz = q.z - z.z, dw = q.w - z.w;
    float s = dx * dx + dy * dy + dz * dz + dw * dw;
    float* es = esum + (size_t)i * GD + d;
    atomicAdd(es + 0, z.x);
    atomicAdd(es + 1, z.y);
    atomicAdd(es + 2, z.z);
    atomicAdd(es + 3, z.w);
#pragma unroll
    for (int o = 16; o; o >>= 1) s += __shfl_down_sync(0xffffffffu, s, o);
    if (lane == 0) sh[w] = s;
    __syncthreads();
    if (t == 0) atomicAdd(&lossPart[n & 511], sh[0] + sh[1] + sh[2] + sh[3]);
}

// ---------------- cluster_size EMA + n reduction ----------------
__global__ void clnew_kernel(const float* __restrict__ cl, const float* __restrict__ counts,
                             float* __restrict__ clnew, float* __restrict__ nsum, int K)
{
    int k = blockIdx.x * 256 + threadIdx.x;
    float v = 0.f;
    if (k < K) {
        v = cl[k] * 0.99f + 0.01f * counts[k];
        clnew[k] = v;
    }
    v = blk_reduce_256(v);
    if (threadIdx.x == 0) atomicAdd(nsum, v);
}

// ---------------- codebook EMA update ----------------
__global__ void cbnew_kernel(const float* __restrict__ avg, const float* __restrict__ esum,
                             const float* __restrict__ clnew, const float* __restrict__ nsum,
                             float* __restrict__ out, int K)
{
    size_t idx = (size_t)blockIdx.x * 256 + threadIdx.x;
    int k = (int)(idx >> 9);
    float n = *nsum;
    float cs = (clnew[k] + 1e-6f) / (n + (float)K * 1e-6f) * n;
    float a = avg[idx] * 0.99f + 0.01f * esum[idx];
    out[idx] = a / cs;
}

__global__ void finalize_loss_kernel(const float* __restrict__ lacc, float* __restrict__ out) {
    __shared__ float sh[8];
    int t = threadIdx.x, lane = t & 31, w = t >> 5;
    float s = lacc[t] + lacc[t + 256];
#pragma unroll
    for (int o = 16; o; o >>= 1) s += __shfl_down_sync(0xffffffffu, s, o);
    if (lane == 0) sh[w] = s;
    __syncthreads();
    if (t == 0) {
        float v = 0.f;
#pragma unroll
        for (int j = 0; j < 8; j++) v += sh[j];
        out[0] = 1.25f * v / 16777216.f;
    }
}

// ---------------- adjacency transform (vector loads, scalar stores) --------
// NOTE: out may be only 4B-aligned (odd element offset in d_out) — scalar STG.
__device__ __forceinline__ float adj1(float a, int c) {
    if (c == 0) return a;
    float p = powf(0.99f, (float)c);
    return fmaf(a, p, (1.f - p) * 100.f);
}
__global__ void adj_kernel(const float* __restrict__ adj, const int* __restrict__ cnt,
                           float* __restrict__ out, size_t total)
{
    size_t i = ((size_t)blockIdx.x * 256 + threadIdx.x) * 4;
    if (i >= total) return;
    int4 c = *(const int4*)(cnt + i);
    float4 a = *(const float4*)(adj + i);
    out[i + 0] = adj1(a.x, c.x);
    out[i + 1] = adj1(a.y, c.y);
    out[i + 2] = adj1(a.z, c.z);
    out[i + 3] = adj1(a.w, c.w);
}

// ---------------- launch ----------------
extern "C" void kernel_launch(void* const* d_in, const int* in_sizes, int n_in,
                              void* d_out, int out_size)
{
    const float* zre_f = (const float*)d_in[0];
    const float* zim_f = (const float*)d_in[1];
    const float* zre_s = (const float*)d_in[2];
    const float* zim_s = (const float*)d_in[3];
    const int*   prev_syn = (const int*)d_in[4];
    const int*   prev_sem = (const int*)d_in[5];
    const float* cb_syn = (const float*)d_in[6];
    const float* cb_sem = (const float*)d_in[7];
    const float* cl_syn = (const float*)d_in[8];
    const float* avg_syn = (const float*)d_in[9];
    const float* cl_sem = (const float*)d_in[10];
    const float* avg_sem = (const float*)d_in[11];
    const float* adj_syn = (const float*)d_in[12];
    const float* adj_sem = (const float*)d_in[13];

    float* out = (float*)d_out;
    const size_t OFF_ZQ_SYN = 0;
    const size_t OFF_ZQ_SEM = OFF_ZQ_SYN + (size_t)GN * GD;
    const size_t OFF_LOSS   = OFF_ZQ_SEM + (size_t)GN * GD;
    const size_t OFF_IDX_SYN = OFF_LOSS + 1;
    const size_t OFF_IDX_SEM = OFF_IDX_SYN + GN;
    const size_t OFF_CB_SYN  = OFF_IDX_SEM + GN;
    const size_t OFF_CB_SEM  = OFF_CB_SYN + (size_t)KS * GD;
    const size_t OFF_ADJ_SYN = OFF_CB_SEM + (size_t)KM * GD;
    const size_t OFF_ADJ_SEM = OFF_ADJ_SYN + (size_t)KS * KS;

    void *p_esum_syn, *p_esum_sem, *p_cnt_syn, *p_cnt_sem, *p_pair_syn, *p_pair_sem;
    void *p_idx_syn, *p_idx_sem, *p_cn_syn, *p_cn_sem, *p_cl_syn, *p_cl_sem, *p_nsum, *p_loss;
    void *p_maxcn, *p_zbf_syn, *p_zbf_sem, *p_cbf_syn, *p_cbf_sem, *p_cv, *p_ck;
    cudaGetSymbolAddress(&p_esum_syn, g_esum_syn);
    cudaGetSymbolAddress(&p_esum_sem, g_esum_sem);
    cudaGetSymbolAddress(&p_cnt_syn, g_counts_syn);
    cudaGetSymbolAddress(&p_cnt_sem, g_counts_sem);
    cudaGetSymbolAddress(&p_pair_syn, g_pair_syn);
    cudaGetSymbolAddress(&p_pair_sem, g_pair_sem);
    cudaGetSymbolAddress(&p_idx_syn, g_idx_syn);
    cudaGetSymbolAddress(&p_idx_sem, g_idx_sem);
    cudaGetSymbolAddress(&p_cn_syn, g_cnorm_syn);
    cudaGetSymbolAddress(&p_cn_sem, g_cnorm_sem);
    cudaGetSymbolAddress(&p_cl_syn, g_clnew_syn);
    cudaGetSymbolAddress(&p_cl_sem, g_clnew_sem);
    cudaGetSymbolAddress(&p_nsum, g_nsum);
    cudaGetSymbolAddress(&p_loss, g_losspart);
    cudaGetSymbolAddress(&p_maxcn, g_maxcn);
    cudaGetSymbolAddress(&p_zbf_syn, g_zbf_syn);
    cudaGetSymbolAddress(&p_zbf_sem, g_zbf_sem);
    cudaGetSymbolAddress(&p_cbf_syn, g_cbf_syn);
    cudaGetSymbolAddress(&p_cbf_sem, g_cbf_sem);
    cudaGetSymbolAddress(&p_cv, g_cv);
    cudaGetSymbolAddress(&p_ck, g_ck);

    cudaFuncSetAttribute(dist_hmma_kernel,
                         cudaFuncAttributeMaxDynamicSharedMemorySize, SM_TOTAL);

    // 1) zero scratch
    cudaMemsetAsync(p_esum_syn, 0, (size_t)KS * GD * sizeof(float));
    cudaMemsetAsync(p_esum_sem, 0, (size_t)KM * GD * sizeof(float));
    cudaMemsetAsync(p_cnt_syn, 0, KS * sizeof(float));
    cudaMemsetAsync(p_cnt_sem, 0, KM * sizeof(float));
    cudaMemsetAsync(p_pair_syn, 0, (size_t)KS * KS * sizeof(int));
    cudaMemsetAsync(p_pair_sem, 0, (size_t)KM * KM * sizeof(int));
    cudaMemsetAsync(p_nsum, 0, 2 * sizeof(float));
    cudaMemsetAsync(p_loss, 0, 512 * sizeof(float));
    cudaMemsetAsync(p_maxcn, 0, 2 * sizeof(int));

    // 2) conversions (+ fused codebook norms)
    cvt_z_kernel<<<(GN * GD) / 1024, 256>>>(zre_f, zim_f, (__nv_bfloat16*)p_zbf_syn);
    cvt_z_kernel<<<(GN * GD) / 1024, 256>>>(zre_s, zim_s, (__nv_bfloat16*)p_zbf_sem);
    cvt_cb_norm_kernel<<<KS / 2, 256>>>(cb_syn, (__nv_bfloat16*)p_cbf_syn,
                                        (float*)p_cn_syn, (int*)p_maxcn);
    cvt_cb_norm_kernel<<<KM / 2, 256>>>(cb_sem, (__nv_bfloat16*)p_cbf_sem,
                                        (float*)p_cn_sem, ((int*)p_maxcn) + 1);

    // 3) HMMA approximate distance pass (deep-pipelined)
    dist_hmma_kernel<<<NUNITS, 256, SM_TOTAL>>>(
        (const __nv_bfloat16*)p_zbf_syn, (const __nv_bfloat16*)p_cbf_syn, (const float*)p_cn_syn,
        (const __nv_bfloat16*)p_zbf_sem, (const __nv_bfloat16*)p_cbf_sem, (const float*)p_cn_sem,
        (float*)p_cv, (int*)p_ck);

    // 4) exact fp32 refinement -> final indices
    refine_kernel<<<(2 * GN) / 8, 256>>>(
        zre_f, zim_f, cb_syn, (const float*)p_cn_syn,
        zre_s, zim_s, cb_sem, (const float*)p_cn_sem,
        (const float*)p_cv, (const int*)p_ck, (const int*)p_maxcn,
        (int*)p_idx_syn, (int*)p_idx_sem);

    // 5) fused per-row scatter + zq + loss
    fuse_row_kernel<<<GN, 128>>>(zre_f, zim_f, (const int*)p_idx_syn, prev_syn, cb_syn,
                                 (float*)p_cnt_syn, (float*)p_esum_syn, (int*)p_pair_syn, KS,
                                 out + OFF_ZQ_SYN, out + OFF_IDX_SYN, (float*)p_loss);
    fuse_row_kernel<<<GN, 128>>>(zre_s, zim_s, (const int*)p_idx_sem, prev_sem, cb_sem,
                                 (float*)p_cnt_sem, (float*)p_esum_sem, (int*)p_pair_sem, KM,
                                 out + OFF_ZQ_SEM, out + OFF_IDX_SEM, (float*)p_loss);

    // 6) cluster size EMA + n
    clnew_kernel<<<KS / 256, 256>>>(cl_syn, (const float*)p_cnt_syn,
                                    (float*)p_cl_syn, (float*)p_nsum, KS);
    clnew_kernel<<<KM / 256, 256>>>(cl_sem, (const float*)p_cnt_sem,
                                    (float*)p_cl_sem, ((float*)p_nsum) + 1, KM);

    // 7) codebook EMA update
    cbnew_kernel<<<(KS * GD) / 256, 256>>>(avg_syn, (const float*)p_esum_syn,
                                           (const float*)p_cl_syn, (const float*)p_nsum,
                                           out + OFF_CB_SYN, KS);
    cbnew_kernel<<<(KM * GD) / 256, 256>>>(avg_sem, (const float*)p_esum_sem,
                                           (const float*)p_cl_sem, ((const float*)p_nsum) + 1,
                                           out + OFF_CB_SEM, KM);

    // 8) loss finalize
    finalize_loss_kernel<<<1, 256>>>((const float*)p_loss, out + OFF_LOSS);

    // 9) adjacency transform
    {
        size_t tot = (size_t)KS * KS;
        adj_kernel<<<(unsigned)(tot / 1024), 256>>>(adj_syn, (const int*)p_pair_syn,
                                                    out + OFF_ADJ_SYN, tot);
    }
    {
        size_t tot = (size_t)KM * KM;
        adj_kernel<<<(unsigned)(tot / 1024), 256>>>(adj_sem, (const int*)p_pair_sem,
                                                    out + OFF_ADJ_SEM, tot);
    }
    (void)in_sizes; (void)n_in; (void)out_size;
}